// round 1
// baseline (speedup 1.0000x reference)
#include <cuda_runtime.h>
#include <math.h>

// Problem constants
constexpr int cB  = 8;
constexpr int cSQ = 512;
constexpr int cSK = 1024;
constexpr int cD  = 1024;
constexpr int cH  = 16;
constexpr int cDK = 64;
constexpr int cF  = 4096;

// ---------------------------------------------------------------------------
// Scratch (device globals; no allocations allowed)
// ---------------------------------------------------------------------------
__device__ float g_bufQ [(size_t)cB*cSQ*cD];        // 4M
__device__ float g_bufK [(size_t)cB*cSK*cD];        // 8M
__device__ float g_bufV [(size_t)cB*cSK*cD];        // 8M
__device__ float g_bufS [(size_t)cB*cH*cSQ*cSQ];    // 32M (self-attn scores)
__device__ float g_bufC [(size_t)cB*cSQ*cD];        // 4M (attention context)
__device__ float g_bufO [(size_t)cB*cSQ*cD];        // 4M (proj/FFN result)
__device__ float g_bufX1[(size_t)cB*cSQ*cD];        // 4M
__device__ float g_bufX2[(size_t)cB*cSQ*cD];        // 4M
__device__ float g_bufF [(size_t)cB*cSQ*cF];        // 16M

// ---------------------------------------------------------------------------
// SGEMM: C[M,N] = A[M,K] @ W[K,N] + bias, optional ReLU.
// 128x128x8 tiling, 256 threads, 8x8 per-thread micro-tile, fp32.
// All M,N,K here are multiples of 128/8 -> no bounds checks.
// ---------------------------------------------------------------------------
template<bool RELU>
__global__ __launch_bounds__(256) void sgemm_bias_kernel(
    const float* __restrict__ A, const float* __restrict__ W,
    const float* __restrict__ bias, float* __restrict__ C,
    int M, int N, int K)
{
    __shared__ float As[8][128];
    __shared__ float Bs[8][128];
    const int tid = threadIdx.x;
    const int bx = blockIdx.x, by = blockIdx.y;
    const int tx = tid & 15, ty = tid >> 4;

    const int a_row = tid >> 1;          // 0..127
    const int a_col = (tid & 1) * 4;     // 0 or 4
    const int b_row = tid >> 5;          // 0..7
    const int b_col = (tid & 31) * 4;    // 0..124

    const float* Aptr = A + (size_t)(by*128 + a_row)*K + a_col;
    const float* Bptr = W + (size_t)b_row*N + bx*128 + b_col;

    float acc[8][8] = {};

    for (int k0 = 0; k0 < K; k0 += 8) {
        float4 av = *(const float4*)(Aptr + k0);
        float4 bv = *(const float4*)(Bptr + (size_t)k0*N);
        As[a_col+0][a_row] = av.x;
        As[a_col+1][a_row] = av.y;
        As[a_col+2][a_row] = av.z;
        As[a_col+3][a_row] = av.w;
        *(float4*)&Bs[b_row][b_col] = bv;
        __syncthreads();
#pragma unroll
        for (int kk = 0; kk < 8; kk++) {
            float4 a0 = *(const float4*)&As[kk][ty*8];
            float4 a1 = *(const float4*)&As[kk][ty*8+4];
            float4 b0 = *(const float4*)&Bs[kk][tx*8];
            float4 b1 = *(const float4*)&Bs[kk][tx*8+4];
            float ar[8] = {a0.x,a0.y,a0.z,a0.w,a1.x,a1.y,a1.z,a1.w};
            float br[8] = {b0.x,b0.y,b0.z,b0.w,b1.x,b1.y,b1.z,b1.w};
#pragma unroll
            for (int i = 0; i < 8; i++)
#pragma unroll
                for (int j = 0; j < 8; j++)
                    acc[i][j] = fmaf(ar[i], br[j], acc[i][j]);
        }
        __syncthreads();
    }

#pragma unroll
    for (int i = 0; i < 8; i++) {
        size_t row = (size_t)by*128 + ty*8 + i;
        float* crow = C + row*(size_t)N + bx*128 + tx*8;
        const float* brow = bias + bx*128 + tx*8;
#pragma unroll
        for (int j = 0; j < 8; j++) {
            float v = acc[i][j] + brow[j];
            if (RELU) v = fmaxf(v, 0.0f);
            crow[j] = v;
        }
    }
}

// ---------------------------------------------------------------------------
// QK^T: S[b,h,q,k] = scale * dot(Q[b,q,h*64:], K[b,k,h*64:]) with causal /
// kv masking. One block = 64x64 tile of S. grid = (sk/64, SQ/64, B*H).
// ---------------------------------------------------------------------------
__global__ __launch_bounds__(256) void qk_kernel(
    const float* __restrict__ Q, const float* __restrict__ Km,
    float* __restrict__ S, const int* __restrict__ kvmask,
    int sk, int causal, float scale)
{
    __shared__ float Qs[64][65];   // [dk][q_local]
    __shared__ float Ks[64][65];   // [dk][k_local]
    const int bh = blockIdx.z;
    const int b  = bh >> 4;        // / cH
    const int h  = bh & 15;
    const int q0 = blockIdx.y * 64;
    const int k0 = blockIdx.x * 64;
    const int tid = threadIdx.x;
    const int tx = tid & 15, ty = tid >> 4;

    if (causal && k0 > q0 + 63) {   // whole tile above diagonal
#pragma unroll
        for (int i = 0; i < 4; i++) {
            int q = q0 + ty*4 + i;
            float* srow = S + ((size_t)bh*cSQ + q)*sk + k0 + tx*4;
#pragma unroll
            for (int j = 0; j < 4; j++) srow[j] = -INFINITY;
        }
        return;
    }

    const float* Qbase = Q + ((size_t)b*cSQ + q0)*cD + h*cDK;
    const float* Kbase = Km + ((size_t)b*sk + k0)*cD + h*cDK;
#pragma unroll
    for (int it = 0; it < 4; it++) {
        int i = tid + it*256;                 // 0..1023
        int r = i >> 4, c4 = (i & 15) * 4;    // 64 rows x 16 f4
        float4 v = *(const float4*)(Qbase + (size_t)r*cD + c4);
        Qs[c4+0][r] = v.x; Qs[c4+1][r] = v.y; Qs[c4+2][r] = v.z; Qs[c4+3][r] = v.w;
        float4 w = *(const float4*)(Kbase + (size_t)r*cD + c4);
        Ks[c4+0][r] = w.x; Ks[c4+1][r] = w.y; Ks[c4+2][r] = w.z; Ks[c4+3][r] = w.w;
    }
    __syncthreads();

    float acc[4][4] = {};
#pragma unroll 16
    for (int kk = 0; kk < 64; kk++) {
        float a[4], bb[4];
#pragma unroll
        for (int i = 0; i < 4; i++) a[i]  = Qs[kk][ty*4+i];
#pragma unroll
        for (int j = 0; j < 4; j++) bb[j] = Ks[kk][tx*4+j];
#pragma unroll
        for (int i = 0; i < 4; i++)
#pragma unroll
            for (int j = 0; j < 4; j++)
                acc[i][j] = fmaf(a[i], bb[j], acc[i][j]);
    }

#pragma unroll
    for (int i = 0; i < 4; i++) {
        int q = q0 + ty*4 + i;
        float* srow = S + ((size_t)bh*cSQ + q)*sk;
#pragma unroll
        for (int j = 0; j < 4; j++) {
            int k = k0 + tx*4 + j;
            float v = acc[i][j] * scale;
            if (causal && k > q) v = -INFINITY;
            if (kvmask && kvmask[b*sk + k] == 0) v = -INFINITY;
            srow[k] = v;
        }
    }
}

// ---------------------------------------------------------------------------
// Row softmax in place. One block (256 threads) per row of length L.
// ---------------------------------------------------------------------------
__global__ __launch_bounds__(256) void softmax_kernel(float* __restrict__ S, int L)
{
    __shared__ float red[256];
    float* p = S + (size_t)blockIdx.x * L;
    const int t = threadIdx.x;

    float m = -INFINITY;
    for (int i = t; i < L; i += 256) m = fmaxf(m, p[i]);
    red[t] = m; __syncthreads();
    for (int s = 128; s > 0; s >>= 1) {
        if (t < s) red[t] = fmaxf(red[t], red[t+s]);
        __syncthreads();
    }
    m = red[0]; __syncthreads();

    float sum = 0.f;
    for (int i = t; i < L; i += 256) {
        float e = __expf(p[i] - m);
        p[i] = e;
        sum += e;
    }
    red[t] = sum; __syncthreads();
    for (int s = 128; s > 0; s >>= 1) {
        if (t < s) red[t] += red[t+s];
        __syncthreads();
    }
    float inv = 1.0f / red[0];
    for (int i = t; i < L; i += 256) p[i] *= inv;
}

// ---------------------------------------------------------------------------
// A @ V: O[b,q,h*64+d] = sum_k P[b,h,q,k] * V[b,k,h*64+d].
// Block = 64 q-rows x full head (64). grid = (SQ/64, B*H).
// ---------------------------------------------------------------------------
__global__ __launch_bounds__(256) void av_kernel(
    const float* __restrict__ P, const float* __restrict__ V,
    float* __restrict__ O, int sk, int causal)
{
    __shared__ float Ps[32][65];   // [k_local][q_local]
    __shared__ float Vs[32][68];   // [k_local][d_local] (68*4B = 272B, 16B aligned rows)
    const int bh = blockIdx.y;
    const int b  = bh >> 4, h = bh & 15;
    const int q0 = blockIdx.x * 64;
    const int tid = threadIdx.x;
    const int tx = tid & 15, ty = tid >> 4;

    const float* Pbase = P + ((size_t)bh*cSQ + q0)*sk;
    const float* Vbase = V + ((size_t)b*sk)*cD + h*cDK;

    float acc[4][4] = {};
    const int kend = causal ? (q0 + 64) : sk;   // P is exactly 0 beyond diag
    for (int k0 = 0; k0 < kend; k0 += 32) {
#pragma unroll
        for (int it = 0; it < 2; it++) {
            int i = tid + it*256;               // 0..511
            {   // P tile: 64 rows x 32 cols (8 f4/row), transpose into Ps
                int r = i >> 3, c4 = (i & 7) * 4;
                float4 v = *(const float4*)(Pbase + (size_t)r*sk + k0 + c4);
                Ps[c4+0][r] = v.x; Ps[c4+1][r] = v.y; Ps[c4+2][r] = v.z; Ps[c4+3][r] = v.w;
            }
            {   // V tile: 32 rows x 64 cols (16 f4/row), direct
                int r = i >> 4, c4 = (i & 15) * 4;
                *(float4*)&Vs[r][c4] = *(const float4*)(Vbase + (size_t)(k0+r)*cD + c4);
            }
        }
        __syncthreads();
#pragma unroll
        for (int kk = 0; kk < 32; kk++) {
            float a[4], bb[4];
#pragma unroll
            for (int i = 0; i < 4; i++) a[i]  = Ps[kk][ty*4+i];
#pragma unroll
            for (int j = 0; j < 4; j++) bb[j] = Vs[kk][tx*4+j];
#pragma unroll
            for (int i = 0; i < 4; i++)
#pragma unroll
                for (int j = 0; j < 4; j++)
                    acc[i][j] = fmaf(a[i], bb[j], acc[i][j]);
        }
        __syncthreads();
    }

#pragma unroll
    for (int i = 0; i < 4; i++) {
        size_t row = (size_t)b*cSQ + q0 + ty*4 + i;
        float* orow = O + row*(size_t)cD + h*cDK + tx*4;
#pragma unroll
        for (int j = 0; j < 4; j++) orow[j] = acc[i][j];
    }
}

// ---------------------------------------------------------------------------
// out = LayerNorm(X + R) * g + b over last dim (D=1024). One block per row.
// ---------------------------------------------------------------------------
__global__ __launch_bounds__(256) void ln_residual_kernel(
    const float* __restrict__ X, const float* __restrict__ R,
    const float* __restrict__ g, const float* __restrict__ be,
    float* __restrict__ out)
{
    __shared__ float red[256];
    const size_t row = blockIdx.x;
    const int t = threadIdx.x;
    const float* xr = X + row*cD;
    const float* rr = R + row*cD;

    float v[4]; float s = 0.f;
#pragma unroll
    for (int i = 0; i < 4; i++) { v[i] = xr[t + i*256] + rr[t + i*256]; s += v[i]; }
    red[t] = s; __syncthreads();
    for (int k = 128; k > 0; k >>= 1) { if (t < k) red[t] += red[t+k]; __syncthreads(); }
    float mu = red[0] * (1.0f / cD); __syncthreads();

    float vs = 0.f;
#pragma unroll
    for (int i = 0; i < 4; i++) { float d = v[i] - mu; vs += d*d; }
    red[t] = vs; __syncthreads();
    for (int k = 128; k > 0; k >>= 1) { if (t < k) red[t] += red[t+k]; __syncthreads(); }
    float inv = rsqrtf(red[0] * (1.0f / cD) + 1e-5f);

    float* orow = out + row*cD;
#pragma unroll
    for (int i = 0; i < 4; i++) {
        int c = t + i*256;
        orow[c] = (v[i] - mu) * inv * g[c] + be[c];
    }
}

// ---------------------------------------------------------------------------
// Launch
// ---------------------------------------------------------------------------
extern "C" void kernel_launch(void* const* d_in, const int* in_sizes, int n_in,
                              void* d_out, int out_size)
{
    const float* x        = (const float*)d_in[0];
    const float* enc_o    = (const float*)d_in[1];
    const int*   enc_mask = (const int*)  d_in[2];
    const float* a1_wq = (const float*)d_in[3];
    const float* a1_bq = (const float*)d_in[4];
    const float* a1_wk = (const float*)d_in[5];
    const float* a1_bk = (const float*)d_in[6];
    const float* a1_wv = (const float*)d_in[7];
    const float* a1_bv = (const float*)d_in[8];
    const float* a1_wo = (const float*)d_in[9];
    const float* a1_bo = (const float*)d_in[10];
    const float* a2_wq = (const float*)d_in[11];
    const float* a2_bq = (const float*)d_in[12];
    const float* a2_wk = (const float*)d_in[13];
    const float* a2_bk = (const float*)d_in[14];
    const float* a2_wv = (const float*)d_in[15];
    const float* a2_bv = (const float*)d_in[16];
    const float* a2_wo = (const float*)d_in[17];
    const float* a2_bo = (const float*)d_in[18];
    const float* ff_w1 = (const float*)d_in[19];
    const float* ff_b1 = (const float*)d_in[20];
    const float* ff_w2 = (const float*)d_in[21];
    const float* ff_b2 = (const float*)d_in[22];
    const float* ln1_g = (const float*)d_in[23];
    const float* ln1_b = (const float*)d_in[24];
    const float* ln2_g = (const float*)d_in[25];
    const float* ln2_b = (const float*)d_in[26];
    const float* ln3_g = (const float*)d_in[27];
    const float* ln3_b = (const float*)d_in[28];

    float* out_x    = (float*)d_out;
    float* out_attn = out_x + (size_t)cB*cSQ*cD;   // attn: [B,H,SQ,SK]

    float *bufQ, *bufK, *bufV, *bufS, *bufC, *bufO, *bufX1, *bufX2, *bufF;
    cudaGetSymbolAddress((void**)&bufQ,  g_bufQ);
    cudaGetSymbolAddress((void**)&bufK,  g_bufK);
    cudaGetSymbolAddress((void**)&bufV,  g_bufV);
    cudaGetSymbolAddress((void**)&bufS,  g_bufS);
    cudaGetSymbolAddress((void**)&bufC,  g_bufC);
    cudaGetSymbolAddress((void**)&bufO,  g_bufO);
    cudaGetSymbolAddress((void**)&bufX1, g_bufX1);
    cudaGetSymbolAddress((void**)&bufX2, g_bufX2);
    cudaGetSymbolAddress((void**)&bufF,  g_bufF);

    const float scale = 0.125f;   // 1/sqrt(64)
    const dim3 blk(256);
    const int M1 = cB * cSQ;      // 4096
    const int M2 = cB * cSK;      // 8192

    // ---- self-attention (causal) ----
    sgemm_bias_kernel<false><<<dim3(cD/128, M1/128), blk>>>(x, a1_wq, a1_bq, bufQ, M1, cD, cD);
    sgemm_bias_kernel<false><<<dim3(cD/128, M1/128), blk>>>(x, a1_wk, a1_bk, bufK, M1, cD, cD);
    sgemm_bias_kernel<false><<<dim3(cD/128, M1/128), blk>>>(x, a1_wv, a1_bv, bufV, M1, cD, cD);
    qk_kernel<<<dim3(cSQ/64, cSQ/64, cB*cH), blk>>>(bufQ, bufK, bufS, nullptr, cSQ, 1, scale);
    softmax_kernel<<<cB*cH*cSQ, blk>>>(bufS, cSQ);
    av_kernel<<<dim3(cSQ/64, cB*cH), blk>>>(bufS, bufV, bufC, cSQ, 1);
    sgemm_bias_kernel<false><<<dim3(cD/128, M1/128), blk>>>(bufC, a1_wo, a1_bo, bufO, M1, cD, cD);
    ln_residual_kernel<<<M1, blk>>>(x, bufO, ln1_g, ln1_b, bufX1);

    // ---- cross-attention (kv mask); probs go straight into d_out ----
    sgemm_bias_kernel<false><<<dim3(cD/128, M1/128), blk>>>(bufX1, a2_wq, a2_bq, bufQ, M1, cD, cD);
    sgemm_bias_kernel<false><<<dim3(cD/128, M2/128), blk>>>(enc_o, a2_wk, a2_bk, bufK, M2, cD, cD);
    sgemm_bias_kernel<false><<<dim3(cD/128, M2/128), blk>>>(enc_o, a2_wv, a2_bv, bufV, M2, cD, cD);
    qk_kernel<<<dim3(cSK/64, cSQ/64, cB*cH), blk>>>(bufQ, bufK, out_attn, enc_mask, cSK, 0, scale);
    softmax_kernel<<<cB*cH*cSQ, blk>>>(out_attn, cSK);
    av_kernel<<<dim3(cSQ/64, cB*cH), blk>>>(out_attn, bufV, bufC, cSK, 0);
    sgemm_bias_kernel<false><<<dim3(cD/128, M1/128), blk>>>(bufC, a2_wo, a2_bo, bufO, M1, cD, cD);
    ln_residual_kernel<<<M1, blk>>>(bufX1, bufO, ln2_g, ln2_b, bufX2);

    // ---- feed-forward ----
    sgemm_bias_kernel<true ><<<dim3(cF/128, M1/128), blk>>>(bufX2, ff_w1, ff_b1, bufF, M1, cF, cD);
    sgemm_bias_kernel<false><<<dim3(cD/128, M1/128), blk>>>(bufF, ff_w2, ff_b2, bufO, M1, cD, cF);
    ln_residual_kernel<<<M1, blk>>>(bufX2, bufO, ln3_g, ln3_b, out_x);
}

// round 2
// speedup vs baseline: 1.0027x; 1.0027x over previous
#include <cuda_runtime.h>
#include <math.h>

// Problem constants
constexpr int cB  = 8;
constexpr int cSQ = 512;
constexpr int cSK = 1024;
constexpr int cD  = 1024;
constexpr int cH  = 16;
constexpr int cDK = 64;
constexpr int cF  = 4096;

// ---------------------------------------------------------------------------
// Scratch (device globals; no allocations allowed)
// ---------------------------------------------------------------------------
__device__ float g_bufQ [(size_t)cB*cSQ*cD];        // 4M
__device__ float g_bufK [(size_t)cB*cSK*cD];        // 8M
__device__ float g_bufV [(size_t)cB*cSK*cD];        // 8M
__device__ float g_bufS [(size_t)cB*cH*cSQ*cSQ];    // 32M (self-attn scores)
__device__ float g_bufC [(size_t)cB*cSQ*cD];        // 4M (attention context)
__device__ float g_bufO [(size_t)cB*cSQ*cD];        // 4M (proj/FFN result)
__device__ float g_bufX1[(size_t)cB*cSQ*cD];        // 4M
__device__ float g_bufX2[(size_t)cB*cSQ*cD];        // 4M
__device__ float g_bufF [(size_t)cB*cSQ*cF];        // 16M

// ---------------------------------------------------------------------------
// SGEMM: C[M,N] = A[M,K] @ W[K,N] + bias, optional ReLU.
// 128x128x8 tiling, 256 threads, 8x8 per-thread micro-tile, fp32.
// All M,N,K here are multiples of 128/8 -> no bounds checks.
// ---------------------------------------------------------------------------
template<bool RELU>
__global__ __launch_bounds__(256) void sgemm_bias_kernel(
    const float* __restrict__ A, const float* __restrict__ W,
    const float* __restrict__ bias, float* __restrict__ C,
    int M, int N, int K)
{
    __shared__ float As[8][128];
    __shared__ float Bs[8][128];
    const int tid = threadIdx.x;
    const int bx = blockIdx.x, by = blockIdx.y;
    const int tx = tid & 15, ty = tid >> 4;

    const int a_row = tid >> 1;          // 0..127
    const int a_col = (tid & 1) * 4;     // 0 or 4
    const int b_row = tid >> 5;          // 0..7
    const int b_col = (tid & 31) * 4;    // 0..124

    const float* Aptr = A + (size_t)(by*128 + a_row)*K + a_col;
    const float* Bptr = W + (size_t)b_row*N + bx*128 + b_col;

    float acc[8][8] = {};

    for (int k0 = 0; k0 < K; k0 += 8) {
        float4 av = *(const float4*)(Aptr + k0);
        float4 bv = *(const float4*)(Bptr + (size_t)k0*N);
        As[a_col+0][a_row] = av.x;
        As[a_col+1][a_row] = av.y;
        As[a_col+2][a_row] = av.z;
        As[a_col+3][a_row] = av.w;
        *(float4*)&Bs[b_row][b_col] = bv;
        __syncthreads();
#pragma unroll
        for (int kk = 0; kk < 8; kk++) {
            float4 a0 = *(const float4*)&As[kk][ty*8];
            float4 a1 = *(const float4*)&As[kk][ty*8+4];
            float4 b0 = *(const float4*)&Bs[kk][tx*8];
            float4 b1 = *(const float4*)&Bs[kk][tx*8+4];
            float ar[8] = {a0.x,a0.y,a0.z,a0.w,a1.x,a1.y,a1.z,a1.w};
            float br[8] = {b0.x,b0.y,b0.z,b0.w,b1.x,b1.y,b1.z,b1.w};
#pragma unroll
            for (int i = 0; i < 8; i++)
#pragma unroll
                for (int j = 0; j < 8; j++)
                    acc[i][j] = fmaf(ar[i], br[j], acc[i][j]);
        }
        __syncthreads();
    }

#pragma unroll
    for (int i = 0; i < 8; i++) {
        size_t row = (size_t)by*128 + ty*8 + i;
        float* crow = C + row*(size_t)N + bx*128 + tx*8;
        const float* brow = bias + bx*128 + tx*8;
#pragma unroll
        for (int j = 0; j < 8; j++) {
            float v = acc[i][j] + brow[j];
            if (RELU) v = fmaxf(v, 0.0f);
            crow[j] = v;
        }
    }
}

// ---------------------------------------------------------------------------
// QK^T: S[b,h,q,k] = scale * dot(Q[b,q,h*64:], K[b,k,h*64:]) with causal /
// kv masking. One block = 64x64 tile of S. grid = (sk/64, SQ/64, B*H).
// ---------------------------------------------------------------------------
__global__ __launch_bounds__(256) void qk_kernel(
    const float* __restrict__ Q, const float* __restrict__ Km,
    float* __restrict__ S, const int* __restrict__ kvmask,
    int sk, int causal, float scale)
{
    __shared__ float Qs[64][65];   // [dk][q_local]
    __shared__ float Ks[64][65];   // [dk][k_local]
    const int bh = blockIdx.z;
    const int b  = bh >> 4;        // / cH
    const int h  = bh & 15;
    const int q0 = blockIdx.y * 64;
    const int k0 = blockIdx.x * 64;
    const int tid = threadIdx.x;
    const int tx = tid & 15, ty = tid >> 4;

    if (causal && k0 > q0 + 63) {   // whole tile above diagonal
#pragma unroll
        for (int i = 0; i < 4; i++) {
            int q = q0 + ty*4 + i;
            float* srow = S + ((size_t)bh*cSQ + q)*sk + k0 + tx*4;
#pragma unroll
            for (int j = 0; j < 4; j++) srow[j] = -INFINITY;
        }
        return;
    }

    const float* Qbase = Q + ((size_t)b*cSQ + q0)*cD + h*cDK;
    const float* Kbase = Km + ((size_t)b*sk + k0)*cD + h*cDK;
#pragma unroll
    for (int it = 0; it < 4; it++) {
        int i = tid + it*256;                 // 0..1023
        int r = i >> 4, c4 = (i & 15) * 4;    // 64 rows x 16 f4
        float4 v = *(const float4*)(Qbase + (size_t)r*cD + c4);
        Qs[c4+0][r] = v.x; Qs[c4+1][r] = v.y; Qs[c4+2][r] = v.z; Qs[c4+3][r] = v.w;
        float4 w = *(const float4*)(Kbase + (size_t)r*cD + c4);
        Ks[c4+0][r] = w.x; Ks[c4+1][r] = w.y; Ks[c4+2][r] = w.z; Ks[c4+3][r] = w.w;
    }
    __syncthreads();

    float acc[4][4] = {};
#pragma unroll 16
    for (int kk = 0; kk < 64; kk++) {
        float a[4], bb[4];
#pragma unroll
        for (int i = 0; i < 4; i++) a[i]  = Qs[kk][ty*4+i];
#pragma unroll
        for (int j = 0; j < 4; j++) bb[j] = Ks[kk][tx*4+j];
#pragma unroll
        for (int i = 0; i < 4; i++)
#pragma unroll
            for (int j = 0; j < 4; j++)
                acc[i][j] = fmaf(a[i], bb[j], acc[i][j]);
    }

#pragma unroll
    for (int i = 0; i < 4; i++) {
        int q = q0 + ty*4 + i;
        float* srow = S + ((size_t)bh*cSQ + q)*sk;
#pragma unroll
        for (int j = 0; j < 4; j++) {
            int k = k0 + tx*4 + j;
            float v = acc[i][j] * scale;
            if (causal && k > q) v = -INFINITY;
            if (kvmask && kvmask[b*sk + k] == 0) v = -INFINITY;
            srow[k] = v;
        }
    }
}

// ---------------------------------------------------------------------------
// Row softmax in place. One block (256 threads) per row of length L.
// ---------------------------------------------------------------------------
__global__ __launch_bounds__(256) void softmax_kernel(float* __restrict__ S, int L)
{
    __shared__ float red[256];
    float* p = S + (size_t)blockIdx.x * L;
    const int t = threadIdx.x;

    float m = -INFINITY;
    for (int i = t; i < L; i += 256) m = fmaxf(m, p[i]);
    red[t] = m; __syncthreads();
    for (int s = 128; s > 0; s >>= 1) {
        if (t < s) red[t] = fmaxf(red[t], red[t+s]);
        __syncthreads();
    }
    m = red[0]; __syncthreads();

    float sum = 0.f;
    for (int i = t; i < L; i += 256) {
        float e = __expf(p[i] - m);
        p[i] = e;
        sum += e;
    }
    red[t] = sum; __syncthreads();
    for (int s = 128; s > 0; s >>= 1) {
        if (t < s) red[t] += red[t+s];
        __syncthreads();
    }
    float inv = 1.0f / red[0];
    for (int i = t; i < L; i += 256) p[i] *= inv;
}

// ---------------------------------------------------------------------------
// A @ V: O[b,q,h*64+d] = sum_k P[b,h,q,k] * V[b,k,h*64+d].
// Block = 64 q-rows x full head (64). grid = (SQ/64, B*H).
// ---------------------------------------------------------------------------
__global__ __launch_bounds__(256) void av_kernel(
    const float* __restrict__ P, const float* __restrict__ V,
    float* __restrict__ O, int sk, int causal)
{
    __shared__ float Ps[32][65];   // [k_local][q_local]
    __shared__ float Vs[32][68];   // [k_local][d_local] (68*4B = 272B, 16B aligned rows)
    const int bh = blockIdx.y;
    const int b  = bh >> 4, h = bh & 15;
    const int q0 = blockIdx.x * 64;
    const int tid = threadIdx.x;
    const int tx = tid & 15, ty = tid >> 4;

    const float* Pbase = P + ((size_t)bh*cSQ + q0)*sk;
    const float* Vbase = V + ((size_t)b*sk)*cD + h*cDK;

    float acc[4][4] = {};
    const int kend = causal ? (q0 + 64) : sk;   // P is exactly 0 beyond diag
    for (int k0 = 0; k0 < kend; k0 += 32) {
#pragma unroll
        for (int it = 0; it < 2; it++) {
            int i = tid + it*256;               // 0..511
            {   // P tile: 64 rows x 32 cols (8 f4/row), transpose into Ps
                int r = i >> 3, c4 = (i & 7) * 4;
                float4 v = *(const float4*)(Pbase + (size_t)r*sk + k0 + c4);
                Ps[c4+0][r] = v.x; Ps[c4+1][r] = v.y; Ps[c4+2][r] = v.z; Ps[c4+3][r] = v.w;
            }
            {   // V tile: 32 rows x 64 cols (16 f4/row), direct
                int r = i >> 4, c4 = (i & 15) * 4;
                *(float4*)&Vs[r][c4] = *(const float4*)(Vbase + (size_t)(k0+r)*cD + c4);
            }
        }
        __syncthreads();
#pragma unroll
        for (int kk = 0; kk < 32; kk++) {
            float a[4], bb[4];
#pragma unroll
            for (int i = 0; i < 4; i++) a[i]  = Ps[kk][ty*4+i];
#pragma unroll
            for (int j = 0; j < 4; j++) bb[j] = Vs[kk][tx*4+j];
#pragma unroll
            for (int i = 0; i < 4; i++)
#pragma unroll
                for (int j = 0; j < 4; j++)
                    acc[i][j] = fmaf(a[i], bb[j], acc[i][j]);
        }
        __syncthreads();
    }

#pragma unroll
    for (int i = 0; i < 4; i++) {
        size_t row = (size_t)b*cSQ + q0 + ty*4 + i;
        float* orow = O + row*(size_t)cD + h*cDK + tx*4;
#pragma unroll
        for (int j = 0; j < 4; j++) orow[j] = acc[i][j];
    }
}

// ---------------------------------------------------------------------------
// out = LayerNorm(X + R) * g + b over last dim (D=1024). One block per row.
// ---------------------------------------------------------------------------
__global__ __launch_bounds__(256) void ln_residual_kernel(
    const float* __restrict__ X, const float* __restrict__ R,
    const float* __restrict__ g, const float* __restrict__ be,
    float* __restrict__ out)
{
    __shared__ float red[256];
    const size_t row = blockIdx.x;
    const int t = threadIdx.x;
    const float* xr = X + row*cD;
    const float* rr = R + row*cD;

    float v[4]; float s = 0.f;
#pragma unroll
    for (int i = 0; i < 4; i++) { v[i] = xr[t + i*256] + rr[t + i*256]; s += v[i]; }
    red[t] = s; __syncthreads();
    for (int k = 128; k > 0; k >>= 1) { if (t < k) red[t] += red[t+k]; __syncthreads(); }
    float mu = red[0] * (1.0f / cD); __syncthreads();

    float vs = 0.f;
#pragma unroll
    for (int i = 0; i < 4; i++) { float d = v[i] - mu; vs += d*d; }
    red[t] = vs; __syncthreads();
    for (int k = 128; k > 0; k >>= 1) { if (t < k) red[t] += red[t+k]; __syncthreads(); }
    float inv = rsqrtf(red[0] * (1.0f / cD) + 1e-5f);

    float* orow = out + row*cD;
#pragma unroll
    for (int i = 0; i < 4; i++) {
        int c = t + i*256;
        orow[c] = (v[i] - mu) * inv * g[c] + be[c];
    }
}

// ---------------------------------------------------------------------------
// Launch
// ---------------------------------------------------------------------------
extern "C" void kernel_launch(void* const* d_in, const int* in_sizes, int n_in,
                              void* d_out, int out_size)
{
    const float* x        = (const float*)d_in[0];
    const float* enc_o    = (const float*)d_in[1];
    const int*   enc_mask = (const int*)  d_in[2];
    const float* a1_wq = (const float*)d_in[3];
    const float* a1_bq = (const float*)d_in[4];
    const float* a1_wk = (const float*)d_in[5];
    const float* a1_bk = (const float*)d_in[6];
    const float* a1_wv = (const float*)d_in[7];
    const float* a1_bv = (const float*)d_in[8];
    const float* a1_wo = (const float*)d_in[9];
    const float* a1_bo = (const float*)d_in[10];
    const float* a2_wq = (const float*)d_in[11];
    const float* a2_bq = (const float*)d_in[12];
    const float* a2_wk = (const float*)d_in[13];
    const float* a2_bk = (const float*)d_in[14];
    const float* a2_wv = (const float*)d_in[15];
    const float* a2_bv = (const float*)d_in[16];
    const float* a2_wo = (const float*)d_in[17];
    const float* a2_bo = (const float*)d_in[18];
    const float* ff_w1 = (const float*)d_in[19];
    const float* ff_b1 = (const float*)d_in[20];
    const float* ff_w2 = (const float*)d_in[21];
    const float* ff_b2 = (const float*)d_in[22];
    const float* ln1_g = (const float*)d_in[23];
    const float* ln1_b = (const float*)d_in[24];
    const float* ln2_g = (const float*)d_in[25];
    const float* ln2_b = (const float*)d_in[26];
    const float* ln3_g = (const float*)d_in[27];
    const float* ln3_b = (const float*)d_in[28];

    float* out_x    = (float*)d_out;
    float* out_attn = out_x + (size_t)cB*cSQ*cD;   // attn: [B,H,SQ,SK]

    float *bufQ, *bufK, *bufV, *bufS, *bufC, *bufO, *bufX1, *bufX2, *bufF;
    cudaGetSymbolAddress((void**)&bufQ,  g_bufQ);
    cudaGetSymbolAddress((void**)&bufK,  g_bufK);
    cudaGetSymbolAddress((void**)&bufV,  g_bufV);
    cudaGetSymbolAddress((void**)&bufS,  g_bufS);
    cudaGetSymbolAddress((void**)&bufC,  g_bufC);
    cudaGetSymbolAddress((void**)&bufO,  g_bufO);
    cudaGetSymbolAddress((void**)&bufX1, g_bufX1);
    cudaGetSymbolAddress((void**)&bufX2, g_bufX2);
    cudaGetSymbolAddress((void**)&bufF,  g_bufF);

    const float scale = 0.125f;   // 1/sqrt(64)
    const dim3 blk(256);
    const int M1 = cB * cSQ;      // 4096
    const int M2 = cB * cSK;      // 8192

    // ---- self-attention (causal) ----
    sgemm_bias_kernel<false><<<dim3(cD/128, M1/128), blk>>>(x, a1_wq, a1_bq, bufQ, M1, cD, cD);
    sgemm_bias_kernel<false><<<dim3(cD/128, M1/128), blk>>>(x, a1_wk, a1_bk, bufK, M1, cD, cD);
    sgemm_bias_kernel<false><<<dim3(cD/128, M1/128), blk>>>(x, a1_wv, a1_bv, bufV, M1, cD, cD);
    qk_kernel<<<dim3(cSQ/64, cSQ/64, cB*cH), blk>>>(bufQ, bufK, bufS, nullptr, cSQ, 1, scale);
    softmax_kernel<<<cB*cH*cSQ, blk>>>(bufS, cSQ);
    av_kernel<<<dim3(cSQ/64, cB*cH), blk>>>(bufS, bufV, bufC, cSQ, 1);
    sgemm_bias_kernel<false><<<dim3(cD/128, M1/128), blk>>>(bufC, a1_wo, a1_bo, bufO, M1, cD, cD);
    ln_residual_kernel<<<M1, blk>>>(x, bufO, ln1_g, ln1_b, bufX1);

    // ---- cross-attention (kv mask); probs go straight into d_out ----
    sgemm_bias_kernel<false><<<dim3(cD/128, M1/128), blk>>>(bufX1, a2_wq, a2_bq, bufQ, M1, cD, cD);
    sgemm_bias_kernel<false><<<dim3(cD/128, M2/128), blk>>>(enc_o, a2_wk, a2_bk, bufK, M2, cD, cD);
    sgemm_bias_kernel<false><<<dim3(cD/128, M2/128), blk>>>(enc_o, a2_wv, a2_bv, bufV, M2, cD, cD);
    qk_kernel<<<dim3(cSK/64, cSQ/64, cB*cH), blk>>>(bufQ, bufK, out_attn, enc_mask, cSK, 0, scale);
    softmax_kernel<<<cB*cH*cSQ, blk>>>(out_attn, cSK);
    av_kernel<<<dim3(cSQ/64, cB*cH), blk>>>(out_attn, bufV, bufC, cSK, 0);
    sgemm_bias_kernel<false><<<dim3(cD/128, M1/128), blk>>>(bufC, a2_wo, a2_bo, bufO, M1, cD, cD);
    ln_residual_kernel<<<M1, blk>>>(bufX1, bufO, ln2_g, ln2_b, bufX2);

    // ---- feed-forward ----
    sgemm_bias_kernel<true ><<<dim3(cF/128, M1/128), blk>>>(bufX2, ff_w1, ff_b1, bufF, M1, cF, cD);
    sgemm_bias_kernel<false><<<dim3(cD/128, M1/128), blk>>>(bufF, ff_w2, ff_b2, bufO, M1, cD, cF);
    ln_residual_kernel<<<M1, blk>>>(bufX2, bufO, ln3_g, ln3_b, out_x);
}

// round 3
// speedup vs baseline: 2.6752x; 2.6679x over previous
#include <cuda_runtime.h>
#include <math.h>
#include <stdint.h>

// Problem constants
constexpr int cB  = 8;
constexpr int cSQ = 512;
constexpr int cSK = 1024;
constexpr int cD  = 1024;
constexpr int cH  = 16;
constexpr int cDK = 64;
constexpr int cF  = 4096;

// ---------------------------------------------------------------------------
// Scratch (device globals; no allocations allowed)
// ---------------------------------------------------------------------------
__device__ float g_bufQ [(size_t)cB*cSQ*cD];
__device__ float g_bufK [(size_t)cB*cSK*cD];
__device__ float g_bufV [(size_t)cB*cSK*cD];
__device__ float g_bufS [(size_t)cB*cH*cSQ*cSQ];
__device__ float g_bufC [(size_t)cB*cSQ*cD];
__device__ float g_bufO [(size_t)cB*cSQ*cD];
__device__ float g_bufX1[(size_t)cB*cSQ*cD];
__device__ float g_bufX2[(size_t)cB*cSQ*cD];
__device__ float g_bufF [(size_t)cB*cSQ*cF];

// ---------------------------------------------------------------------------
// tf32 helpers
// ---------------------------------------------------------------------------
__device__ __forceinline__ uint32_t f2tf(float f) {
    uint32_t r;
    asm("cvt.rna.tf32.f32 %0, %1;" : "=r"(r) : "f"(f));
    return r;
}

__device__ __forceinline__ void mma_tf32(float c[4],
    uint32_t a0, uint32_t a1, uint32_t a2, uint32_t a3,
    uint32_t b0, uint32_t b1)
{
    asm volatile(
        "mma.sync.aligned.m16n8k8.row.col.f32.tf32.tf32.f32 "
        "{%0,%1,%2,%3}, {%4,%5,%6,%7}, {%8,%9}, {%0,%1,%2,%3};"
        : "+f"(c[0]), "+f"(c[1]), "+f"(c[2]), "+f"(c[3])
        : "r"(a0), "r"(a1), "r"(a2), "r"(a3), "r"(b0), "r"(b1));
}

// ---------------------------------------------------------------------------
// tf32 tensor-core GEMM: C[M,N] = A[M,K] @ W[K,N] + bias, optional ReLU.
// Block 128x128, k-step 32, 8 warps (2x4), warp tile 64x32.
// As: [m][k] stride 36 (≡4 mod 32 -> conflict-free A-frag LDS)
// Bs: [k][n] stride 136 (≡8 mod 32 -> conflict-free B-frag LDS)
// ---------------------------------------------------------------------------
template<bool RELU>
__global__ __launch_bounds__(256) void gemm_tf32_kernel(
    const float* __restrict__ A, const float* __restrict__ W,
    const float* __restrict__ bias, float* __restrict__ C,
    int M, int N, int K)
{
    __shared__ uint32_t As[128 * 36];
    __shared__ uint32_t Bs[32 * 136];

    const int tid  = threadIdx.x;
    const int bx   = blockIdx.x, by = blockIdx.y;
    const int warp = tid >> 5, lane = tid & 31;
    const int g    = lane >> 2;      // 0..7
    const int tig  = lane & 3;       // 0..3
    const int wm   = warp >> 2;      // 0..1  (64 rows each)
    const int wn   = warp & 3;       // 0..3  (32 cols each)

    float acc[4][4][4] = {};

    for (int k0 = 0; k0 < K; k0 += 32) {
        // A tile 128x32
#pragma unroll
        for (int it = 0; it < 4; it++) {
            int idx = tid + it * 256;
            int r = idx >> 3, c4 = (idx & 7) * 4;
            float4 v = *(const float4*)(A + (size_t)(by*128 + r)*K + k0 + c4);
            uint4 u = { f2tf(v.x), f2tf(v.y), f2tf(v.z), f2tf(v.w) };
            *(uint4*)&As[r*36 + c4] = u;
        }
        // B tile 32x128
#pragma unroll
        for (int it = 0; it < 4; it++) {
            int idx = tid + it * 256;
            int r = idx >> 5, c4 = (idx & 31) * 4;
            float4 v = *(const float4*)(W + (size_t)(k0 + r)*N + bx*128 + c4);
            uint4 u = { f2tf(v.x), f2tf(v.y), f2tf(v.z), f2tf(v.w) };
            *(uint4*)&Bs[r*136 + c4] = u;
        }
        __syncthreads();

#pragma unroll
        for (int kk = 0; kk < 32; kk += 8) {
            uint32_t bf[4][2];
#pragma unroll
            for (int nt = 0; nt < 4; nt++) {
                int n = wn*32 + nt*8 + g;
                bf[nt][0] = Bs[(kk + tig)*136 + n];
                bf[nt][1] = Bs[(kk + 4 + tig)*136 + n];
            }
            uint32_t af[4][4];
#pragma unroll
            for (int mt = 0; mt < 4; mt++) {
                int r0 = wm*64 + mt*16 + g;
                af[mt][0] = As[r0*36 + kk + tig];
                af[mt][1] = As[(r0 + 8)*36 + kk + tig];
                af[mt][2] = As[r0*36 + kk + 4 + tig];
                af[mt][3] = As[(r0 + 8)*36 + kk + 4 + tig];
            }
#pragma unroll
            for (int mt = 0; mt < 4; mt++)
#pragma unroll
                for (int nt = 0; nt < 4; nt++)
                    mma_tf32(acc[mt][nt], af[mt][0], af[mt][1], af[mt][2], af[mt][3],
                             bf[nt][0], bf[nt][1]);
        }
        __syncthreads();
    }

#pragma unroll
    for (int mt = 0; mt < 4; mt++) {
#pragma unroll
        for (int nt = 0; nt < 4; nt++) {
            int row0 = by*128 + wm*64 + mt*16 + g;
            int col  = bx*128 + wn*32 + nt*8 + 2*tig;
            float b0 = bias[col], b1 = bias[col + 1];
            float2 v0 = { acc[mt][nt][0] + b0, acc[mt][nt][1] + b1 };
            float2 v1 = { acc[mt][nt][2] + b0, acc[mt][nt][3] + b1 };
            if (RELU) {
                v0.x = fmaxf(v0.x, 0.f); v0.y = fmaxf(v0.y, 0.f);
                v1.x = fmaxf(v1.x, 0.f); v1.y = fmaxf(v1.y, 0.f);
            }
            *(float2*)&C[(size_t)row0*N + col]       = v0;
            *(float2*)&C[(size_t)(row0 + 8)*N + col] = v1;
        }
    }
}

// ---------------------------------------------------------------------------
// QK^T via tf32 mma. Block = 64 q x 64 k. grid = (sk/64, SQ/64, B*H).
// Qs: [q][d] stride 68 (A frags, ≡4 mod 32). Ks: [kpos][d] stride 68;
// B (col-major) fragments read it by index math (bank-clean, no transpose).
// ---------------------------------------------------------------------------
__global__ __launch_bounds__(256) void qk_mma_kernel(
    const float* __restrict__ Q, const float* __restrict__ Km,
    float* __restrict__ S, const int* __restrict__ kvmask,
    int sk, int causal, float scale)
{
    __shared__ uint32_t Qs[64 * 68];
    __shared__ uint32_t Ks[64 * 68];
    __shared__ int msk[64];

    const int bh = blockIdx.z;
    const int b  = bh >> 4, h = bh & 15;
    const int q0 = blockIdx.y * 64;
    const int k0 = blockIdx.x * 64;
    const int tid  = threadIdx.x;
    const int warp = tid >> 5, lane = tid & 31;
    const int g = lane >> 2, tig = lane & 3;
    const int wm = warp >> 2;   // 0..1 -> 32 q-rows
    const int wn = warp & 3;    // 0..3 -> 16 k-cols

    if (causal && k0 > q0 + 63) {
        float4 ninf = { -INFINITY, -INFINITY, -INFINITY, -INFINITY };
#pragma unroll
        for (int it = 0; it < 4; it++) {
            int idx = tid + it * 256;
            int r = idx >> 4, c4 = (idx & 15) * 4;
            *(float4*)(S + ((size_t)bh*cSQ + q0 + r)*sk + k0 + c4) = ninf;
        }
        return;
    }

    const float* Qbase = Q  + ((size_t)b*cSQ + q0)*cD + h*cDK;
    const float* Kbase = Km + ((size_t)b*sk  + k0)*cD + h*cDK;
#pragma unroll
    for (int it = 0; it < 4; it++) {
        int idx = tid + it * 256;
        int r = idx >> 4, c4 = (idx & 15) * 4;
        float4 v = *(const float4*)(Qbase + (size_t)r*cD + c4);
        uint4 u = { f2tf(v.x), f2tf(v.y), f2tf(v.z), f2tf(v.w) };
        *(uint4*)&Qs[r*68 + c4] = u;
        float4 w = *(const float4*)(Kbase + (size_t)r*cD + c4);
        uint4 t = { f2tf(w.x), f2tf(w.y), f2tf(w.z), f2tf(w.w) };
        *(uint4*)&Ks[r*68 + c4] = t;
    }
    if (kvmask && tid < 64) msk[tid] = kvmask[b*sk + k0 + tid];
    __syncthreads();

    float acc[2][2][4] = {};
#pragma unroll
    for (int kk = 0; kk < 64; kk += 8) {
        uint32_t bf[2][2];
#pragma unroll
        for (int nt = 0; nt < 2; nt++) {
            int n = wn*16 + nt*8 + g;                 // k-position (mma col)
            bf[nt][0] = Ks[n*68 + kk + tig];          // row = head-dim
            bf[nt][1] = Ks[n*68 + kk + 4 + tig];
        }
        uint32_t af[2][4];
#pragma unroll
        for (int mt = 0; mt < 2; mt++) {
            int r0 = wm*32 + mt*16 + g;
            af[mt][0] = Qs[r0*68 + kk + tig];
            af[mt][1] = Qs[(r0 + 8)*68 + kk + tig];
            af[mt][2] = Qs[r0*68 + kk + 4 + tig];
            af[mt][3] = Qs[(r0 + 8)*68 + kk + 4 + tig];
        }
#pragma unroll
        for (int mt = 0; mt < 2; mt++)
#pragma unroll
            for (int nt = 0; nt < 2; nt++)
                mma_tf32(acc[mt][nt], af[mt][0], af[mt][1], af[mt][2], af[mt][3],
                         bf[nt][0], bf[nt][1]);
    }

#pragma unroll
    for (int mt = 0; mt < 2; mt++) {
#pragma unroll
        for (int nt = 0; nt < 2; nt++) {
            int qrow = q0 + wm*32 + mt*16 + g;
            int kl   = wn*16 + nt*8 + 2*tig;          // local k column
            int kcol = k0 + kl;
            bool m0 = kvmask && msk[kl] == 0;
            bool m1 = kvmask && msk[kl + 1] == 0;
#pragma unroll
            for (int rr = 0; rr < 2; rr++) {
                int q = qrow + rr*8;
                float v0 = acc[mt][nt][rr*2 + 0] * scale;
                float v1 = acc[mt][nt][rr*2 + 1] * scale;
                if ((causal && kcol     > q) || m0) v0 = -INFINITY;
                if ((causal && kcol + 1 > q) || m1) v1 = -INFINITY;
                float2 v = { v0, v1 };
                *(float2*)&S[((size_t)bh*cSQ + q)*sk + kcol] = v;
            }
        }
    }
}

// ---------------------------------------------------------------------------
// A @ V via tf32 mma. Block = 64 q x 64 d (one head). grid = (SQ/64, B*H).
// Ps: [q][kpos] stride 36. Vs: [kpos][d] stride 72.
// ---------------------------------------------------------------------------
__global__ __launch_bounds__(256) void av_mma_kernel(
    const float* __restrict__ P, const float* __restrict__ V,
    float* __restrict__ O, int sk, int causal)
{
    __shared__ uint32_t Ps[64 * 36];
    __shared__ uint32_t Vs[32 * 72];

    const int bh = blockIdx.y;
    const int b  = bh >> 4, h = bh & 15;
    const int q0 = blockIdx.x * 64;
    const int tid  = threadIdx.x;
    const int warp = tid >> 5, lane = tid & 31;
    const int g = lane >> 2, tig = lane & 3;
    const int wm = warp >> 2;   // 0..1
    const int wn = warp & 3;    // 0..3

    const float* Pbase = P + ((size_t)bh*cSQ + q0)*sk;
    const float* Vbase = V + ((size_t)b*sk)*cD + h*cDK;

    float acc[2][2][4] = {};
    const int kend = causal ? (q0 + 64) : sk;

    for (int k0 = 0; k0 < kend; k0 += 32) {
#pragma unroll
        for (int it = 0; it < 2; it++) {
            int idx = tid + it * 256;
            {   // P tile 64x32
                int r = idx >> 3, c4 = (idx & 7) * 4;
                float4 v = *(const float4*)(Pbase + (size_t)r*sk + k0 + c4);
                uint4 u = { f2tf(v.x), f2tf(v.y), f2tf(v.z), f2tf(v.w) };
                *(uint4*)&Ps[r*36 + c4] = u;
            }
            {   // V tile 32x64
                int r = idx >> 4, c4 = (idx & 15) * 4;
                float4 v = *(const float4*)(Vbase + (size_t)(k0 + r)*cD + c4);
                uint4 u = { f2tf(v.x), f2tf(v.y), f2tf(v.z), f2tf(v.w) };
                *(uint4*)&Vs[r*72 + c4] = u;
            }
        }
        __syncthreads();

#pragma unroll
        for (int kk = 0; kk < 32; kk += 8) {
            uint32_t bf[2][2];
#pragma unroll
            for (int nt = 0; nt < 2; nt++) {
                int n = wn*16 + nt*8 + g;
                bf[nt][0] = Vs[(kk + tig)*72 + n];
                bf[nt][1] = Vs[(kk + 4 + tig)*72 + n];
            }
            uint32_t af[2][4];
#pragma unroll
            for (int mt = 0; mt < 2; mt++) {
                int r0 = wm*32 + mt*16 + g;
                af[mt][0] = Ps[r0*36 + kk + tig];
                af[mt][1] = Ps[(r0 + 8)*36 + kk + tig];
                af[mt][2] = Ps[r0*36 + kk + 4 + tig];
                af[mt][3] = Ps[(r0 + 8)*36 + kk + 4 + tig];
            }
#pragma unroll
            for (int mt = 0; mt < 2; mt++)
#pragma unroll
                for (int nt = 0; nt < 2; nt++)
                    mma_tf32(acc[mt][nt], af[mt][0], af[mt][1], af[mt][2], af[mt][3],
                             bf[nt][0], bf[nt][1]);
        }
        __syncthreads();
    }

#pragma unroll
    for (int mt = 0; mt < 2; mt++) {
#pragma unroll
        for (int nt = 0; nt < 2; nt++) {
            int qrow = q0 + wm*32 + mt*16 + g;
            int d    = wn*16 + nt*8 + 2*tig;
#pragma unroll
            for (int rr = 0; rr < 2; rr++) {
                size_t row = (size_t)b*cSQ + qrow + rr*8;
                float2 v = { acc[mt][nt][rr*2 + 0], acc[mt][nt][rr*2 + 1] };
                *(float2*)&O[row*cD + h*cDK + d] = v;
            }
        }
    }
}

// ---------------------------------------------------------------------------
// Row softmax in place. One block (256 threads) per row of length L.
// ---------------------------------------------------------------------------
__global__ __launch_bounds__(256) void softmax_kernel(float* __restrict__ S, int L)
{
    __shared__ float red[256];
    float* p = S + (size_t)blockIdx.x * L;
    const int t = threadIdx.x;

    float m = -INFINITY;
    for (int i = t; i < L; i += 256) m = fmaxf(m, p[i]);
    red[t] = m; __syncthreads();
    for (int s = 128; s > 0; s >>= 1) {
        if (t < s) red[t] = fmaxf(red[t], red[t+s]);
        __syncthreads();
    }
    m = red[0]; __syncthreads();

    float sum = 0.f;
    for (int i = t; i < L; i += 256) {
        float e = __expf(p[i] - m);
        p[i] = e;
        sum += e;
    }
    red[t] = sum; __syncthreads();
    for (int s = 128; s > 0; s >>= 1) {
        if (t < s) red[t] += red[t+s];
        __syncthreads();
    }
    float inv = 1.0f / red[0];
    for (int i = t; i < L; i += 256) p[i] *= inv;
}

// ---------------------------------------------------------------------------
// out = LayerNorm(X + R) * g + b over last dim (D=1024). One block per row.
// ---------------------------------------------------------------------------
__global__ __launch_bounds__(256) void ln_residual_kernel(
    const float* __restrict__ X, const float* __restrict__ R,
    const float* __restrict__ g, const float* __restrict__ be,
    float* __restrict__ out)
{
    __shared__ float red[256];
    const size_t row = blockIdx.x;
    const int t = threadIdx.x;
    const float* xr = X + row*cD;
    const float* rr = R + row*cD;

    float v[4]; float s = 0.f;
#pragma unroll
    for (int i = 0; i < 4; i++) { v[i] = xr[t + i*256] + rr[t + i*256]; s += v[i]; }
    red[t] = s; __syncthreads();
    for (int k = 128; k > 0; k >>= 1) { if (t < k) red[t] += red[t+k]; __syncthreads(); }
    float mu = red[0] * (1.0f / cD); __syncthreads();

    float vs = 0.f;
#pragma unroll
    for (int i = 0; i < 4; i++) { float d = v[i] - mu; vs += d*d; }
    red[t] = vs; __syncthreads();
    for (int k = 128; k > 0; k >>= 1) { if (t < k) red[t] += red[t+k]; __syncthreads(); }
    float inv = rsqrtf(red[0] * (1.0f / cD) + 1e-5f);

    float* orow = out + row*cD;
#pragma unroll
    for (int i = 0; i < 4; i++) {
        int c = t + i*256;
        orow[c] = (v[i] - mu) * inv * g[c] + be[c];
    }
}

// ---------------------------------------------------------------------------
// Launch
// ---------------------------------------------------------------------------
extern "C" void kernel_launch(void* const* d_in, const int* in_sizes, int n_in,
                              void* d_out, int out_size)
{
    const float* x        = (const float*)d_in[0];
    const float* enc_o    = (const float*)d_in[1];
    const int*   enc_mask = (const int*)  d_in[2];
    const float* a1_wq = (const float*)d_in[3];
    const float* a1_bq = (const float*)d_in[4];
    const float* a1_wk = (const float*)d_in[5];
    const float* a1_bk = (const float*)d_in[6];
    const float* a1_wv = (const float*)d_in[7];
    const float* a1_bv = (const float*)d_in[8];
    const float* a1_wo = (const float*)d_in[9];
    const float* a1_bo = (const float*)d_in[10];
    const float* a2_wq = (const float*)d_in[11];
    const float* a2_bq = (const float*)d_in[12];
    const float* a2_wk = (const float*)d_in[13];
    const float* a2_bk = (const float*)d_in[14];
    const float* a2_wv = (const float*)d_in[15];
    const float* a2_bv = (const float*)d_in[16];
    const float* a2_wo = (const float*)d_in[17];
    const float* a2_bo = (const float*)d_in[18];
    const float* ff_w1 = (const float*)d_in[19];
    const float* ff_b1 = (const float*)d_in[20];
    const float* ff_w2 = (const float*)d_in[21];
    const float* ff_b2 = (const float*)d_in[22];
    const float* ln1_g = (const float*)d_in[23];
    const float* ln1_b = (const float*)d_in[24];
    const float* ln2_g = (const float*)d_in[25];
    const float* ln2_b = (const float*)d_in[26];
    const float* ln3_g = (const float*)d_in[27];
    const float* ln3_b = (const float*)d_in[28];

    float* out_x    = (float*)d_out;
    float* out_attn = out_x + (size_t)cB*cSQ*cD;

    float *bufQ, *bufK, *bufV, *bufS, *bufC, *bufO, *bufX1, *bufX2, *bufF;
    cudaGetSymbolAddress((void**)&bufQ,  g_bufQ);
    cudaGetSymbolAddress((void**)&bufK,  g_bufK);
    cudaGetSymbolAddress((void**)&bufV,  g_bufV);
    cudaGetSymbolAddress((void**)&bufS,  g_bufS);
    cudaGetSymbolAddress((void**)&bufC,  g_bufC);
    cudaGetSymbolAddress((void**)&bufO,  g_bufO);
    cudaGetSymbolAddress((void**)&bufX1, g_bufX1);
    cudaGetSymbolAddress((void**)&bufX2, g_bufX2);
    cudaGetSymbolAddress((void**)&bufF,  g_bufF);

    const float scale = 0.125f;   // 1/sqrt(64)
    const dim3 blk(256);
    const int M1 = cB * cSQ;      // 4096
    const int M2 = cB * cSK;      // 8192

    // ---- self-attention (causal) ----
    gemm_tf32_kernel<false><<<dim3(cD/128, M1/128), blk>>>(x, a1_wq, a1_bq, bufQ, M1, cD, cD);
    gemm_tf32_kernel<false><<<dim3(cD/128, M1/128), blk>>>(x, a1_wk, a1_bk, bufK, M1, cD, cD);
    gemm_tf32_kernel<false><<<dim3(cD/128, M1/128), blk>>>(x, a1_wv, a1_bv, bufV, M1, cD, cD);
    qk_mma_kernel<<<dim3(cSQ/64, cSQ/64, cB*cH), blk>>>(bufQ, bufK, bufS, nullptr, cSQ, 1, scale);
    softmax_kernel<<<cB*cH*cSQ, blk>>>(bufS, cSQ);
    av_mma_kernel<<<dim3(cSQ/64, cB*cH), blk>>>(bufS, bufV, bufC, cSQ, 1);
    gemm_tf32_kernel<false><<<dim3(cD/128, M1/128), blk>>>(bufC, a1_wo, a1_bo, bufO, M1, cD, cD);
    ln_residual_kernel<<<M1, blk>>>(x, bufO, ln1_g, ln1_b, bufX1);

    // ---- cross-attention (kv mask); probs go straight into d_out ----
    gemm_tf32_kernel<false><<<dim3(cD/128, M1/128), blk>>>(bufX1, a2_wq, a2_bq, bufQ, M1, cD, cD);
    gemm_tf32_kernel<false><<<dim3(cD/128, M2/128), blk>>>(enc_o, a2_wk, a2_bk, bufK, M2, cD, cD);
    gemm_tf32_kernel<false><<<dim3(cD/128, M2/128), blk>>>(enc_o, a2_wv, a2_bv, bufV, M2, cD, cD);
    qk_mma_kernel<<<dim3(cSK/64, cSQ/64, cB*cH), blk>>>(bufQ, bufK, out_attn, enc_mask, cSK, 0, scale);
    softmax_kernel<<<cB*cH*cSQ, blk>>>(out_attn, cSK);
    av_mma_kernel<<<dim3(cSQ/64, cB*cH), blk>>>(out_attn, bufV, bufC, cSK, 0);
    gemm_tf32_kernel<false><<<dim3(cD/128, M1/128), blk>>>(bufC, a2_wo, a2_bo, bufO, M1, cD, cD);
    ln_residual_kernel<<<M1, blk>>>(bufX1, bufO, ln2_g, ln2_b, bufX2);

    // ---- feed-forward ----
    gemm_tf32_kernel<true ><<<dim3(cF/128, M1/128), blk>>>(bufX2, ff_w1, ff_b1, bufF, M1, cF, cD);
    gemm_tf32_kernel<false><<<dim3(cD/128, M1/128), blk>>>(bufF, ff_w2, ff_b2, bufO, M1, cD, cF);
    ln_residual_kernel<<<M1, blk>>>(bufX2, bufO, ln3_g, ln3_b, out_x);
}